// round 3
// baseline (speedup 1.0000x reference)
#include <cuda_runtime.h>
#include <math.h>
#include <float.h>

#define NN 256
#define CC 128
#define HH 4
#define DD 32
#define MM (NN*NN)     // 65536
#define HD (HH*DD)     // 128
#define INF_ 1e9f
#define LN_EPS 1e-5f

// ---- scratch (no allocation allowed) ----
__device__ float g_xn[MM*CC];
__device__ float g_q [MM*HD];
__device__ float g_k [MM*HD];
__device__ float g_v [MM*HD];
__device__ float g_g [MM*HD];
__device__ float g_o [MM*HD];
__device__ float g_tbt[HH*NN*NN];   // [h][k][j]
__device__ float g_woT[CC*HD];      // [k][n] = wo[n][k]

// ---------------------------------------------------------------
// Kernel 1: LayerNorm (on transposed input) + triangle-bias dots
// one block per row m = i1*N + i2 ; xn[i1][i2][:] = LN(x[i2][i1][:])
// ---------------------------------------------------------------
__global__ void ln_kernel(const float* __restrict__ x,
                          const float* __restrict__ ln_w,
                          const float* __restrict__ ln_b,
                          const float* __restrict__ w_bias)
{
    int m  = blockIdx.x;
    int i1 = m >> 8;
    int i2 = m & 255;
    int c  = threadIdx.x;           // 0..127

    float v = x[(i2*NN + i1)*CC + c];

    __shared__ float red[4];
    // mean
    float s = v;
    #pragma unroll
    for (int o = 16; o > 0; o >>= 1) s += __shfl_xor_sync(0xffffffffu, s, o);
    if ((c & 31) == 0) red[c >> 5] = s;
    __syncthreads();
    float mu = (red[0] + red[1] + red[2] + red[3]) * (1.0f / CC);
    __syncthreads();
    // var (biased)
    float d0 = v - mu;
    float s2 = d0 * d0;
    #pragma unroll
    for (int o = 16; o > 0; o >>= 1) s2 += __shfl_xor_sync(0xffffffffu, s2, o);
    if ((c & 31) == 0) red[c >> 5] = s2;
    __syncthreads();
    float var = (red[0] + red[1] + red[2] + red[3]) * (1.0f / CC);

    float xn = d0 * rsqrtf(var + LN_EPS) * ln_w[c] + ln_b[c];
    g_xn[m*CC + c] = xn;

    // triangle bias: tb[h] = dot(xn_row, w_bias[h][:]); store transposed
    __shared__ float xs[CC];
    xs[c] = xn;
    __syncthreads();
    int w    = c >> 5;
    int lane = c & 31;
    float acc = 0.f;
    #pragma unroll
    for (int cc = 0; cc < CC; cc += 32)
        acc += xs[cc + lane] * w_bias[w*CC + cc + lane];
    #pragma unroll
    for (int o = 16; o > 0; o >>= 1) acc += __shfl_xor_sync(0xffffffffu, acc, o);
    if (lane == 0) g_tbt[(w*NN + i2)*NN + i1] = acc;   // [h][k=i2][j=i1]
}

// ---------------------------------------------------------------
// Kernel 2: projections  q/k/v/g = xn @ W   (W is [128][128] row-major)
// 64x64 tile, 256 threads, 4x4 micro-tile. q gets the 1/sqrt(D) scale.
// ---------------------------------------------------------------
__global__ __launch_bounds__(256)
void gemm_proj(const float* __restrict__ W0, const float* __restrict__ W1,
               const float* __restrict__ W2, const float* __restrict__ W3)
{
    const float* W;
    float* Out;
    float osc = 1.0f;
    switch (blockIdx.z) {
        case 0: W = W0; Out = g_q; osc = 0.17677669529663689f; break; // 1/sqrt(32)
        case 1: W = W1; Out = g_k; break;
        case 2: W = W2; Out = g_v; break;
        default: W = W3; Out = g_g; break;
    }
    int m0 = blockIdx.x * 64;
    int n0 = blockIdx.y * 64;

    __shared__ float As[16][64];   // [k][m]
    __shared__ float Bs[16][64];   // [k][n]

    int tid = threadIdx.x;
    int tm = tid >> 4;         // 0..15
    int tn = tid & 15;         // 0..15

    float acc[4][4] = {};

    for (int k0 = 0; k0 < CC; k0 += 16) {
        // A tile: 64 rows x 16 k
        {
            int r  = tid >> 2;
            int kq = (tid & 3) * 4;
            float4 a4 = *(const float4*)&g_xn[(m0 + r)*CC + k0 + kq];
            As[kq+0][r] = a4.x; As[kq+1][r] = a4.y;
            As[kq+2][r] = a4.z; As[kq+3][r] = a4.w;
        }
        // B tile: 16 k x 64 n
        {
            int kr = tid >> 4;
            int nq = (tid & 15) * 4;
            *(float4*)&Bs[kr][nq] = *(const float4*)&W[(k0 + kr)*HD + n0 + nq];
        }
        __syncthreads();
        #pragma unroll
        for (int kk = 0; kk < 16; kk++) {
            float4 a4 = *(const float4*)&As[kk][tm*4];
            float4 b4 = *(const float4*)&Bs[kk][tn*4];
            float a[4] = {a4.x, a4.y, a4.z, a4.w};
            float b[4] = {b4.x, b4.y, b4.z, b4.w};
            #pragma unroll
            for (int i = 0; i < 4; i++)
                #pragma unroll
                for (int jx = 0; jx < 4; jx++)
                    acc[i][jx] += a[i] * b[jx];
        }
        __syncthreads();
    }
    #pragma unroll
    for (int i = 0; i < 4; i++) {
        int row = m0 + tm*4 + i;
        float4 r4 = make_float4(acc[i][0]*osc, acc[i][1]*osc, acc[i][2]*osc, acc[i][3]*osc);
        *(float4*)&Out[row*HD + n0 + tn*4] = r4;
    }
}

// ---------------------------------------------------------------
// Kernel 3: wo transpose (128x128)
// ---------------------------------------------------------------
__global__ void transpose_wo(const float* __restrict__ wo)
{
    int idx = blockIdx.x * 256 + threadIdx.x;    // 0..16383
    int n = idx >> 7, k = idx & 127;
    g_woT[k*HD + n] = wo[n*HD + k];
}

// ---------------------------------------------------------------
// Kernel 4: attention per (I, h). 256 threads = 256 query rows j.
// Flash-style online softmax over K chunks of 128.
// ---------------------------------------------------------------
__global__ __launch_bounds__(256)
void attn_kernel(const float* __restrict__ mask)
{
    int I = blockIdx.x;
    int h = blockIdx.y;
    int j = threadIdx.x;

    __shared__ float Ks[128][32];
    __shared__ float Vs[128][32];
    __shared__ float mb[NN];

    // mask bias: mb[k] = INF*(mask[k][I]-1)
    mb[j] = INF_ * (mask[j*NN + I] - 1.0f);

    // load q (scale already applied)
    float q[32];
    {
        const float* qp = &g_q[(I*NN + j)*HD + h*DD];
        #pragma unroll
        for (int d4 = 0; d4 < 8; d4++) {
            float4 t = *(const float4*)&qp[d4*4];
            q[d4*4+0] = t.x; q[d4*4+1] = t.y; q[d4*4+2] = t.z; q[d4*4+3] = t.w;
        }
    }

    float o[32];
    #pragma unroll
    for (int d = 0; d < 32; d++) o[d] = 0.f;
    float mrun = -FLT_MAX;
    float ssum = 0.f;

    const float* tbp = &g_tbt[h*NN*NN];   // [k][j]

    for (int kc = 0; kc < NN; kc += 128) {
        __syncthreads();
        // cooperative load K,V chunk [128][32]
        #pragma unroll
        for (int p = 0; p < 4; p++) {
            int slot = p*256 + j;
            int r  = slot >> 3;
            int d4 = (slot & 7) * 4;
            int grow = (I*NN + kc + r)*HD + h*DD + d4;
            *(float4*)&Ks[r][d4] = *(const float4*)&g_k[grow];
            *(float4*)&Vs[r][d4] = *(const float4*)&g_v[grow];
        }
        __syncthreads();

        for (int ks = 0; ks < 128; ks += 32) {
            float sc[32];
            float mx = -FLT_MAX;
            #pragma unroll
            for (int kk = 0; kk < 32; kk++) {
                int k = ks + kk;
                float s = 0.f;
                #pragma unroll
                for (int d4 = 0; d4 < 8; d4++) {
                    float4 kv = *(const float4*)&Ks[k][d4*4];
                    s += q[d4*4+0]*kv.x + q[d4*4+1]*kv.y
                       + q[d4*4+2]*kv.z + q[d4*4+3]*kv.w;
                }
                s += mb[kc + k] + tbp[(kc + k)*NN + j];
                sc[kk] = s;
                mx = fmaxf(mx, s);
            }
            float mnew = fmaxf(mrun, mx);
            float corr = __expf(mrun - mnew);
            ssum *= corr;
            #pragma unroll
            for (int d = 0; d < 32; d++) o[d] *= corr;
            float psum = 0.f;
            #pragma unroll
            for (int kk = 0; kk < 32; kk++) {
                float p = __expf(sc[kk] - mnew);
                sc[kk] = p;
                psum += p;
            }
            ssum += psum;
            mrun = mnew;
            #pragma unroll
            for (int kk = 0; kk < 32; kk++) {
                float p = sc[kk];
                #pragma unroll
                for (int d4 = 0; d4 < 8; d4++) {
                    float4 vv = *(const float4*)&Vs[ks+kk][d4*4];
                    o[d4*4+0] += p*vv.x; o[d4*4+1] += p*vv.y;
                    o[d4*4+2] += p*vv.z; o[d4*4+3] += p*vv.w;
                }
            }
        }
    }

    float inv = 1.0f / ssum;
    float* op = &g_o[(I*NN + j)*HD + h*DD];
    #pragma unroll
    for (int d4 = 0; d4 < 8; d4++) {
        float4 r4 = make_float4(o[d4*4+0]*inv, o[d4*4+1]*inv,
                                o[d4*4+2]*inv, o[d4*4+3]*inv);
        *(float4*)&op[d4*4] = r4;
    }
}

// ---------------------------------------------------------------
// Kernel 5: gated output projection + bias + transposed scatter
// out[(i2*N+i1)*C + n] = sum_k (o[m][k]*sigmoid(g[m][k]+bg[k])) * woT[k][n] + bo[n]
// ---------------------------------------------------------------
__global__ __launch_bounds__(256)
void gemm_out(const float* __restrict__ bg, const float* __restrict__ bo,
              float* __restrict__ out)
{
    int m0 = blockIdx.x * 64;
    int n0 = blockIdx.y * 64;

    __shared__ float As[16][64];
    __shared__ float Bs[16][64];

    int tid = threadIdx.x;
    int tm = tid >> 4;
    int tn = tid & 15;

    float acc[4][4] = {};

    for (int k0 = 0; k0 < HD; k0 += 16) {
        {
            int r  = tid >> 2;
            int kq = (tid & 3) * 4;
            int row = m0 + r;
            float4 o4  = *(const float4*)&g_o[row*HD + k0 + kq];
            float4 g4  = *(const float4*)&g_g[row*HD + k0 + kq];
            float4 bg4 = *(const float4*)&bg[k0 + kq];
            float a0 = o4.x / (1.0f + __expf(-(g4.x + bg4.x)));
            float a1 = o4.y / (1.0f + __expf(-(g4.y + bg4.y)));
            float a2 = o4.z / (1.0f + __expf(-(g4.z + bg4.z)));
            float a3 = o4.w / (1.0f + __expf(-(g4.w + bg4.w)));
            As[kq+0][r] = a0; As[kq+1][r] = a1;
            As[kq+2][r] = a2; As[kq+3][r] = a3;
        }
        {
            int kr = tid >> 4;
            int nq = (tid & 15) * 4;
            *(float4*)&Bs[kr][nq] = *(const float4*)&g_woT[(k0 + kr)*HD + n0 + nq];
        }
        __syncthreads();
        #pragma unroll
        for (int kk = 0; kk < 16; kk++) {
            float4 a4 = *(const float4*)&As[kk][tm*4];
            float4 b4 = *(const float4*)&Bs[kk][tn*4];
            float a[4] = {a4.x, a4.y, a4.z, a4.w};
            float b[4] = {b4.x, b4.y, b4.z, b4.w};
            #pragma unroll
            for (int i = 0; i < 4; i++)
                #pragma unroll
                for (int jx = 0; jx < 4; jx++)
                    acc[i][jx] += a[i] * b[jx];
        }
        __syncthreads();
    }

    float4 bo4 = *(const float4*)&bo[n0 + tn*4];
    #pragma unroll
    for (int i = 0; i < 4; i++) {
        int m  = m0 + tm*4 + i;
        int i1 = m >> 8, i2 = m & 255;
        int orow = i2*NN + i1;          // final swapaxes
        float4 r4 = make_float4(acc[i][0] + bo4.x, acc[i][1] + bo4.y,
                                acc[i][2] + bo4.z, acc[i][3] + bo4.w);
        *(float4*)&out[orow*CC + n0 + tn*4] = r4;
    }
}

// ---------------------------------------------------------------
extern "C" void kernel_launch(void* const* d_in, const int* in_sizes, int n_in,
                              void* d_out, int out_size)
{
    const float* x      = (const float*)d_in[0];
    const float* mask   = (const float*)d_in[1];
    const float* ln_w   = (const float*)d_in[2];
    const float* ln_b   = (const float*)d_in[3];
    const float* w_bias = (const float*)d_in[4];
    const float* wq     = (const float*)d_in[5];
    const float* wk     = (const float*)d_in[6];
    const float* wv     = (const float*)d_in[7];
    const float* wg     = (const float*)d_in[8];
    const float* bg     = (const float*)d_in[9];
    const float* wo     = (const float*)d_in[10];
    const float* bo     = (const float*)d_in[11];
    float* out = (float*)d_out;

    ln_kernel<<<MM, 128>>>(x, ln_w, ln_b, w_bias);
    gemm_proj<<<dim3(MM/64, HD/64, 4), 256>>>(wq, wk, wv, wg);
    transpose_wo<<<64, 256>>>(wo);
    attn_kernel<<<dim3(NN, HH), 256>>>(mask);
    gemm_out<<<dim3(MM/64, CC/64), 256>>>(bg, bo, out);
}

// round 4
// speedup vs baseline: 1.0977x; 1.0977x over previous
#include <cuda_runtime.h>
#include <math.h>
#include <float.h>

#define NN 256
#define CC 128
#define HH 4
#define DD 32
#define MM (NN*NN)     // 65536
#define HD (HH*DD)     // 128
#define INF_ 1e9f
#define LN_EPS 1e-5f

// ---- scratch (no allocation allowed) ----
__device__ float g_xn[MM*CC];
__device__ float g_q [MM*HD];
__device__ float g_k [MM*HD];
__device__ float g_v [MM*HD];
__device__ float g_g [MM*HD];
__device__ float g_o [MM*HD];
__device__ float g_tbt[HH*NN*NN];   // [h][k][j]
__device__ float g_woT[CC*HD];      // [k][n] = wo[n][k]

// ---------------------------------------------------------------
// Kernel 1: LayerNorm (on transposed input) + triangle-bias dots
// ---------------------------------------------------------------
__global__ void ln_kernel(const float* __restrict__ x,
                          const float* __restrict__ ln_w,
                          const float* __restrict__ ln_b,
                          const float* __restrict__ w_bias)
{
    int m  = blockIdx.x;
    int i1 = m >> 8;
    int i2 = m & 255;
    int c  = threadIdx.x;           // 0..127

    float v = x[(i2*NN + i1)*CC + c];

    __shared__ float red[4];
    float s = v;
    #pragma unroll
    for (int o = 16; o > 0; o >>= 1) s += __shfl_xor_sync(0xffffffffu, s, o);
    if ((c & 31) == 0) red[c >> 5] = s;
    __syncthreads();
    float mu = (red[0] + red[1] + red[2] + red[3]) * (1.0f / CC);
    __syncthreads();
    float d0 = v - mu;
    float s2 = d0 * d0;
    #pragma unroll
    for (int o = 16; o > 0; o >>= 1) s2 += __shfl_xor_sync(0xffffffffu, s2, o);
    if ((c & 31) == 0) red[c >> 5] = s2;
    __syncthreads();
    float var = (red[0] + red[1] + red[2] + red[3]) * (1.0f / CC);

    float xn = d0 * rsqrtf(var + LN_EPS) * ln_w[c] + ln_b[c];
    g_xn[m*CC + c] = xn;

    __shared__ float xs[CC];
    xs[c] = xn;
    __syncthreads();
    int w    = c >> 5;
    int lane = c & 31;
    float acc = 0.f;
    #pragma unroll
    for (int cc = 0; cc < CC; cc += 32)
        acc += xs[cc + lane] * w_bias[w*CC + cc + lane];
    #pragma unroll
    for (int o = 16; o > 0; o >>= 1) acc += __shfl_xor_sync(0xffffffffu, acc, o);
    if (lane == 0) g_tbt[(w*NN + i2)*NN + i1] = acc;   // [h][k=i2][j=i1]
}

// ---------------------------------------------------------------
// Kernel 2: projections, 128x128 block tile, 8x8 micro-tile
// grid (MM/128, 1, 4)
// ---------------------------------------------------------------
__global__ __launch_bounds__(256, 2)
void gemm_proj(const float* __restrict__ W0, const float* __restrict__ W1,
               const float* __restrict__ W2, const float* __restrict__ W3)
{
    const float* W;
    float* Out;
    float osc = 1.0f;
    switch (blockIdx.z) {
        case 0: W = W0; Out = g_q; osc = 0.17677669529663689f; break; // 1/sqrt(32)
        case 1: W = W1; Out = g_k; break;
        case 2: W = W2; Out = g_v; break;
        default: W = W3; Out = g_g; break;
    }
    int m0 = blockIdx.x * 128;

    __shared__ float As[16][128];   // [k][m]
    __shared__ float Bs[16][128];   // [k][n]

    int tid = threadIdx.x;
    int tm = tid >> 4;         // 0..15 -> rows tm*8..
    int tn = tid & 15;         // 0..15 -> cols tn*8..

    float acc[8][8] = {};

    for (int k0 = 0; k0 < CC; k0 += 16) {
        #pragma unroll
        for (int i = 0; i < 2; i++) {
            int f = tid*2 + i;            // 0..511
            int r  = f >> 2;              // 0..127
            int kq = (f & 3) * 4;
            float4 a4 = *(const float4*)&g_xn[(m0 + r)*CC + k0 + kq];
            As[kq+0][r] = a4.x; As[kq+1][r] = a4.y;
            As[kq+2][r] = a4.z; As[kq+3][r] = a4.w;
            int kr = f >> 5;              // 0..15
            int nq = (f & 31) * 4;
            *(float4*)&Bs[kr][nq] = *(const float4*)&W[(k0 + kr)*HD + nq];
        }
        __syncthreads();
        #pragma unroll
        for (int kk = 0; kk < 16; kk++) {
            float a[8], b[8];
            *(float4*)&a[0] = *(const float4*)&As[kk][tm*8];
            *(float4*)&a[4] = *(const float4*)&As[kk][tm*8+4];
            *(float4*)&b[0] = *(const float4*)&Bs[kk][tn*8];
            *(float4*)&b[4] = *(const float4*)&Bs[kk][tn*8+4];
            #pragma unroll
            for (int i = 0; i < 8; i++)
                #pragma unroll
                for (int jx = 0; jx < 8; jx++)
                    acc[i][jx] += a[i] * b[jx];
        }
        __syncthreads();
    }
    #pragma unroll
    for (int i = 0; i < 8; i++) {
        int row = m0 + tm*8 + i;
        #pragma unroll
        for (int jq = 0; jq < 2; jq++) {
            float4 r4 = make_float4(acc[i][jq*4+0]*osc, acc[i][jq*4+1]*osc,
                                    acc[i][jq*4+2]*osc, acc[i][jq*4+3]*osc);
            *(float4*)&Out[row*HD + tn*8 + jq*4] = r4;
        }
    }
}

// ---------------------------------------------------------------
// Kernel 3: wo transpose
// ---------------------------------------------------------------
__global__ void transpose_wo(const float* __restrict__ wo)
{
    int idx = blockIdx.x * 256 + threadIdx.x;
    int n = idx >> 7, k = idx & 127;
    g_woT[k*HD + n] = wo[n*HD + k];
}

// ---------------------------------------------------------------
// Kernel 4: attention, split-D: 2 threads per query row (16 dims each)
// grid (I=256, h=4, jb=2), block 256 = 128 rows x 2 halves
// ---------------------------------------------------------------
__global__ __launch_bounds__(256, 2)
void attn_kernel(const float* __restrict__ mask)
{
    int I  = blockIdx.x;
    int h  = blockIdx.y;
    int jb = blockIdx.z;
    int tid  = threadIdx.x;
    int jl   = tid >> 1;           // 0..127
    int half = tid & 1;            // 0..1
    int j = jb*128 + jl;

    __shared__ float Ks[128][32];
    __shared__ float Vs[128][32];
    __shared__ float mb[NN];

    // mask bias for all 256 k
    mb[tid] = INF_ * (mask[tid*NN + I] - 1.0f);

    // q slice (scale pre-applied in projection)
    float q[16];
    {
        const float* qp = &g_q[(I*NN + j)*HD + h*DD + half*16];
        #pragma unroll
        for (int d4 = 0; d4 < 4; d4++)
            *(float4*)&q[d4*4] = *(const float4*)&qp[d4*4];
    }

    float o[16];
    #pragma unroll
    for (int d = 0; d < 16; d++) o[d] = 0.f;
    float mrun = -FLT_MAX;
    float ssum = 0.f;

    const float* tbp = &g_tbt[h*NN*NN];   // [k][j]

    for (int kc = 0; kc < NN; kc += 128) {
        __syncthreads();
        // cooperative load K,V chunk [128][32]: 1024 float4 each, 4/thread
        #pragma unroll
        for (int p = 0; p < 4; p++) {
            int slot = p*256 + tid;       // 0..1023
            int r  = slot >> 3;
            int d4 = (slot & 7) * 4;
            int grow = (I*NN + kc + r)*HD + h*DD + d4;
            *(float4*)&Ks[r][d4] = *(const float4*)&g_k[grow];
            *(float4*)&Vs[r][d4] = *(const float4*)&g_v[grow];
        }
        __syncthreads();

        for (int ks = 0; ks < 128; ks += 16) {
            float sc[16];
            float mx = -FLT_MAX;
            #pragma unroll
            for (int kk = 0; kk < 16; kk++) {
                int k = ks + kk;
                float s = 0.f;
                #pragma unroll
                for (int d4 = 0; d4 < 4; d4++) {
                    float4 kv = *(const float4*)&Ks[k][half*16 + d4*4];
                    s += q[d4*4+0]*kv.x + q[d4*4+1]*kv.y
                       + q[d4*4+2]*kv.z + q[d4*4+3]*kv.w;
                }
                s += __shfl_xor_sync(0xffffffffu, s, 1);   // combine halves
                s += mb[kc + k] + tbp[(kc + k)*NN + j];
                sc[kk] = s;
                mx = fmaxf(mx, s);
            }
            float mnew = fmaxf(mrun, mx);
            float corr = __expf(mrun - mnew);
            ssum *= corr;
            #pragma unroll
            for (int d = 0; d < 16; d++) o[d] *= corr;
            float psum = 0.f;
            #pragma unroll
            for (int kk = 0; kk < 16; kk++) {
                float p = __expf(sc[kk] - mnew);
                sc[kk] = p;
                psum += p;
            }
            ssum += psum;
            mrun = mnew;
            #pragma unroll
            for (int kk = 0; kk < 16; kk++) {
                float p = sc[kk];
                #pragma unroll
                for (int d4 = 0; d4 < 4; d4++) {
                    float4 vv = *(const float4*)&Vs[ks+kk][half*16 + d4*4];
                    o[d4*4+0] += p*vv.x; o[d4*4+1] += p*vv.y;
                    o[d4*4+2] += p*vv.z; o[d4*4+3] += p*vv.w;
                }
            }
        }
    }

    float inv = 1.0f / ssum;
    float* op = &g_o[(I*NN + j)*HD + h*DD + half*16];
    #pragma unroll
    for (int d4 = 0; d4 < 4; d4++) {
        float4 r4 = make_float4(o[d4*4+0]*inv, o[d4*4+1]*inv,
                                o[d4*4+2]*inv, o[d4*4+3]*inv);
        *(float4*)&op[d4*4] = r4;
    }
}

// ---------------------------------------------------------------
// Kernel 5: gated output projection, 128x128 tile, 8x8 micro-tile
// out[(i2*N+i1)*C + n] = sum_k (o*sigmoid(g+bg)) woT[k][n] + bo[n]
// ---------------------------------------------------------------
__global__ __launch_bounds__(256, 2)
void gemm_out(const float* __restrict__ bg, const float* __restrict__ bo,
              float* __restrict__ out)
{
    int m0 = blockIdx.x * 128;

    __shared__ float As[16][128];
    __shared__ float Bs[16][128];

    int tid = threadIdx.x;
    int tm = tid >> 4;
    int tn = tid & 15;

    float acc[8][8] = {};

    for (int k0 = 0; k0 < HD; k0 += 16) {
        #pragma unroll
        for (int i = 0; i < 2; i++) {
            int f = tid*2 + i;
            int r  = f >> 2;
            int kq = (f & 3) * 4;
            int row = m0 + r;
            float4 o4  = *(const float4*)&g_o[row*HD + k0 + kq];
            float4 g4  = *(const float4*)&g_g[row*HD + k0 + kq];
            float4 bg4 = *(const float4*)&bg[k0 + kq];
            As[kq+0][r] = o4.x / (1.0f + __expf(-(g4.x + bg4.x)));
            As[kq+1][r] = o4.y / (1.0f + __expf(-(g4.y + bg4.y)));
            As[kq+2][r] = o4.z / (1.0f + __expf(-(g4.z + bg4.z)));
            As[kq+3][r] = o4.w / (1.0f + __expf(-(g4.w + bg4.w)));
            int kr = f >> 5;
            int nq = (f & 31) * 4;
            *(float4*)&Bs[kr][nq] = *(const float4*)&g_woT[(k0 + kr)*HD + nq];
        }
        __syncthreads();
        #pragma unroll
        for (int kk = 0; kk < 16; kk++) {
            float a[8], b[8];
            *(float4*)&a[0] = *(const float4*)&As[kk][tm*8];
            *(float4*)&a[4] = *(const float4*)&As[kk][tm*8+4];
            *(float4*)&b[0] = *(const float4*)&Bs[kk][tn*8];
            *(float4*)&b[4] = *(const float4*)&Bs[kk][tn*8+4];
            #pragma unroll
            for (int i = 0; i < 8; i++)
                #pragma unroll
                for (int jx = 0; jx < 8; jx++)
                    acc[i][jx] += a[i] * b[jx];
        }
        __syncthreads();
    }

    #pragma unroll
    for (int i = 0; i < 8; i++) {
        int m  = m0 + tm*8 + i;
        int i1 = m >> 8, i2 = m & 255;
        int orow = i2*NN + i1;          // final swapaxes
        #pragma unroll
        for (int jq = 0; jq < 2; jq++) {
            float4 bo4 = *(const float4*)&bo[tn*8 + jq*4];
            float4 r4 = make_float4(acc[i][jq*4+0] + bo4.x, acc[i][jq*4+1] + bo4.y,
                                    acc[i][jq*4+2] + bo4.z, acc[i][jq*4+3] + bo4.w);
            *(float4*)&out[orow*CC + tn*8 + jq*4] = r4;
        }
    }
}

// ---------------------------------------------------------------
extern "C" void kernel_launch(void* const* d_in, const int* in_sizes, int n_in,
                              void* d_out, int out_size)
{
    const float* x      = (const float*)d_in[0];
    const float* mask   = (const float*)d_in[1];
    const float* ln_w   = (const float*)d_in[2];
    const float* ln_b   = (const float*)d_in[3];
    const float* w_bias = (const float*)d_in[4];
    const float* wq     = (const float*)d_in[5];
    const float* wk     = (const float*)d_in[6];
    const float* wv     = (const float*)d_in[7];
    const float* wg     = (const float*)d_in[8];
    const float* bg     = (const float*)d_in[9];
    const float* wo     = (const float*)d_in[10];
    const float* bo     = (const float*)d_in[11];
    float* out = (float*)d_out;

    ln_kernel<<<MM, 128>>>(x, ln_w, ln_b, w_bias);
    gemm_proj<<<dim3(MM/128, 1, 4), 256>>>(wq, wk, wv, wg);
    transpose_wo<<<64, 256>>>(wo);
    attn_kernel<<<dim3(NN, HH, 2), 256>>>(mask);
    gemm_out<<<dim3(MM/128, 1), 256>>>(bg, bo, out);
}

// round 5
// speedup vs baseline: 1.5757x; 1.4354x over previous
#include <cuda_runtime.h>
#include <math.h>
#include <float.h>
#include <stdint.h>

#define NN 256
#define CC 128
#define HH 4
#define DD 32
#define MM (NN*NN)     // 65536
#define HD (HH*DD)     // 128
#define INF_ 1e9f
#define LN_EPS 1e-5f

// ---- scratch (no allocation allowed) ----
__device__ float g_xn[MM*CC];
__device__ float g_q [MM*HD];
__device__ float g_k [MM*HD];
__device__ float g_v [MM*HD];
__device__ float g_g [MM*HD];
__device__ float g_o [MM*HD];
__device__ float g_tbt[HH*NN*NN];   // [h][k][j]
__device__ float g_woT[CC*HD];      // [k][n] = wo[n][k]

// ---------------------------------------------------------------
// tf32 mma helpers
// ---------------------------------------------------------------
__device__ __forceinline__ uint32_t f2tf(float x) {
    uint32_t r;
    asm("cvt.rna.tf32.f32 %0, %1;" : "=r"(r) : "f"(x));
    return r;
}

__device__ __forceinline__ void mma_tf32(float c[4], const uint32_t a[4],
                                         uint32_t b0, uint32_t b1) {
    asm volatile(
        "mma.sync.aligned.m16n8k8.row.col.f32.tf32.tf32.f32 "
        "{%0,%1,%2,%3}, {%4,%5,%6,%7}, {%8,%9}, {%0,%1,%2,%3};\n"
        : "+f"(c[0]), "+f"(c[1]), "+f"(c[2]), "+f"(c[3])
        : "r"(a[0]), "r"(a[1]), "r"(a[2]), "r"(a[3]), "r"(b0), "r"(b1));
}

// ---------------------------------------------------------------
// Kernel 1: LayerNorm (on transposed input) + triangle-bias dots
// ---------------------------------------------------------------
__global__ void ln_kernel(const float* __restrict__ x,
                          const float* __restrict__ ln_w,
                          const float* __restrict__ ln_b,
                          const float* __restrict__ w_bias)
{
    int m  = blockIdx.x;
    int i1 = m >> 8;
    int i2 = m & 255;
    int c  = threadIdx.x;           // 0..127

    float v = x[(i2*NN + i1)*CC + c];

    __shared__ float red[4];
    float s = v;
    #pragma unroll
    for (int o = 16; o > 0; o >>= 1) s += __shfl_xor_sync(0xffffffffu, s, o);
    if ((c & 31) == 0) red[c >> 5] = s;
    __syncthreads();
    float mu = (red[0] + red[1] + red[2] + red[3]) * (1.0f / CC);
    __syncthreads();
    float d0 = v - mu;
    float s2 = d0 * d0;
    #pragma unroll
    for (int o = 16; o > 0; o >>= 1) s2 += __shfl_xor_sync(0xffffffffu, s2, o);
    if ((c & 31) == 0) red[c >> 5] = s2;
    __syncthreads();
    float var = (red[0] + red[1] + red[2] + red[3]) * (1.0f / CC);

    float xn = d0 * rsqrtf(var + LN_EPS) * ln_w[c] + ln_b[c];
    g_xn[m*CC + c] = xn;

    __shared__ float xs[CC];
    xs[c] = xn;
    __syncthreads();
    int w    = c >> 5;
    int lane = c & 31;
    float acc = 0.f;
    #pragma unroll
    for (int cc = 0; cc < CC; cc += 32)
        acc += xs[cc + lane] * w_bias[w*CC + cc + lane];
    #pragma unroll
    for (int o = 16; o > 0; o >>= 1) acc += __shfl_xor_sync(0xffffffffu, acc, o);
    if (lane == 0) g_tbt[(w*NN + i2)*NN + i1] = acc;   // [h][k=i2][j=i1]
}

// ---------------------------------------------------------------
// Kernel 2: projections, 128x128 block tile, 8x8 micro-tile
// ---------------------------------------------------------------
__global__ __launch_bounds__(256, 2)
void gemm_proj(const float* __restrict__ W0, const float* __restrict__ W1,
               const float* __restrict__ W2, const float* __restrict__ W3)
{
    const float* W;
    float* Out;
    float osc = 1.0f;
    switch (blockIdx.z) {
        case 0: W = W0; Out = g_q; osc = 0.17677669529663689f; break; // 1/sqrt(32)
        case 1: W = W1; Out = g_k; break;
        case 2: W = W2; Out = g_v; break;
        default: W = W3; Out = g_g; break;
    }
    int m0 = blockIdx.x * 128;

    __shared__ float As[16][128];   // [k][m]
    __shared__ float Bs[16][128];   // [k][n]

    int tid = threadIdx.x;
    int tm = tid >> 4;
    int tn = tid & 15;

    float acc[8][8] = {};

    for (int k0 = 0; k0 < CC; k0 += 16) {
        #pragma unroll
        for (int i = 0; i < 2; i++) {
            int f = tid*2 + i;            // 0..511
            int r  = f >> 2;              // 0..127
            int kq = (f & 3) * 4;
            float4 a4 = *(const float4*)&g_xn[(m0 + r)*CC + k0 + kq];
            As[kq+0][r] = a4.x; As[kq+1][r] = a4.y;
            As[kq+2][r] = a4.z; As[kq+3][r] = a4.w;
            int kr = f >> 5;              // 0..15
            int nq = (f & 31) * 4;
            *(float4*)&Bs[kr][nq] = *(const float4*)&W[(k0 + kr)*HD + nq];
        }
        __syncthreads();
        #pragma unroll
        for (int kk = 0; kk < 16; kk++) {
            float a[8], b[8];
            *(float4*)&a[0] = *(const float4*)&As[kk][tm*8];
            *(float4*)&a[4] = *(const float4*)&As[kk][tm*8+4];
            *(float4*)&b[0] = *(const float4*)&Bs[kk][tn*8];
            *(float4*)&b[4] = *(const float4*)&Bs[kk][tn*8+4];
            #pragma unroll
            for (int i = 0; i < 8; i++)
                #pragma unroll
                for (int jx = 0; jx < 8; jx++)
                    acc[i][jx] += a[i] * b[jx];
        }
        __syncthreads();
    }
    #pragma unroll
    for (int i = 0; i < 8; i++) {
        int row = m0 + tm*8 + i;
        #pragma unroll
        for (int jq = 0; jq < 2; jq++) {
            float4 r4 = make_float4(acc[i][jq*4+0]*osc, acc[i][jq*4+1]*osc,
                                    acc[i][jq*4+2]*osc, acc[i][jq*4+3]*osc);
            *(float4*)&Out[row*HD + tn*8 + jq*4] = r4;
        }
    }
}

// ---------------------------------------------------------------
// Kernel 3: wo transpose
// ---------------------------------------------------------------
__global__ void transpose_wo(const float* __restrict__ wo)
{
    int idx = blockIdx.x * 256 + threadIdx.x;
    int n = idx >> 7, k = idx & 127;
    g_woT[k*HD + n] = wo[n*HD + k];
}

// ---------------------------------------------------------------
// Kernel 4: tf32 mma flash attention. One block per (I,h), 8 warps,
// each warp owns 32 query rows. K/V fully smem-resident.
// Ks stride 36 (bank = 4g+t conflict-free for QK B-frags),
// Vs stride 40 (bank = 8t+g conflict-free for PV B-frags).
// ---------------------------------------------------------------
#define KS_STR 36
#define VS_STR 40
#define ATTN_SMEM ((NN*KS_STR + NN*VS_STR + NN) * 4)

__global__ __launch_bounds__(256, 1)
void attn_mma(const float* __restrict__ mask)
{
    extern __shared__ float sm[];
    float* Ks = sm;                       // [256][36]
    float* Vs = sm + NN*KS_STR;           // [256][40]
    float* mb = sm + NN*KS_STR + NN*VS_STR; // [256]

    int I = blockIdx.x, h = blockIdx.y;
    int tid  = threadIdx.x;
    int warp = tid >> 5, lane = tid & 31;
    int g = lane >> 2, t = lane & 3;

    // cooperative K/V load
    const float* kbase = g_k + (size_t)(I*NN)*HD + h*DD;
    const float* vbase = g_v + (size_t)(I*NN)*HD + h*DD;
    #pragma unroll
    for (int p = 0; p < 8; p++) {
        int slot = p*256 + tid;           // 0..2047
        int key = slot >> 3;
        int d4  = (slot & 7) * 4;
        *(float4*)&Ks[key*KS_STR + d4] = *(const float4*)&kbase[key*HD + d4];
        *(float4*)&Vs[key*VS_STR + d4] = *(const float4*)&vbase[key*HD + d4];
    }
    mb[tid] = INF_ * (mask[tid*NN + I] - 1.0f);

    // resident Q fragments (scale applied in projection)
    int q0 = warp * 32;
    const float* qbase = g_q + (size_t)(I*NN)*HD + h*DD;
    uint32_t aq[2][4][4];
    #pragma unroll
    for (int mt = 0; mt < 2; mt++)
        #pragma unroll
        for (int ks = 0; ks < 4; ks++)
            #pragma unroll
            for (int r = 0; r < 4; r++) {
                int row = q0 + mt*16 + (r & 1)*8 + g;
                int col = ks*8 + t + (r >> 1)*4;
                aq[mt][ks][r] = f2tf(qbase[row*HD + col]);
            }

    float Of[2][4][4] = {};
    float mrow[2][2] = {{-FLT_MAX, -FLT_MAX}, {-FLT_MAX, -FLT_MAX}};
    float lrow[2][2] = {{0.f, 0.f}, {0.f, 0.f}};

    const float* tbp = g_tbt + h*NN*NN;   // [k][j]

    __syncthreads();

    for (int kc = 0; kc < NN; kc += 64) {
        // ---- S = Q K^T for 64-key chunk ----
        float S[2][8][4] = {};
        #pragma unroll
        for (int nt = 0; nt < 8; nt++) {
            int n0 = kc + nt*8;
            #pragma unroll
            for (int ks = 0; ks < 4; ks++) {
                uint32_t b0 = f2tf(Ks[(n0 + g)*KS_STR + ks*8 + t]);
                uint32_t b1 = f2tf(Ks[(n0 + g)*KS_STR + ks*8 + t + 4]);
                mma_tf32(S[0][nt], aq[0][ks], b0, b1);
                mma_tf32(S[1][nt], aq[1][ks], b0, b1);
            }
        }
        // ---- biases (fp32) ----
        #pragma unroll
        for (int mt = 0; mt < 2; mt++)
            #pragma unroll
            for (int nt = 0; nt < 8; nt++)
                #pragma unroll
                for (int r = 0; r < 4; r++) {
                    int k   = kc + nt*8 + t*2 + (r & 1);
                    int row = q0 + mt*16 + (r >> 1)*8 + g;
                    S[mt][nt][r] += mb[k] + tbp[k*NN + row];
                }
        // ---- online softmax per row state (mt,u) ----
        #pragma unroll
        for (int mt = 0; mt < 2; mt++)
            #pragma unroll
            for (int u = 0; u < 2; u++) {
                float mx = -FLT_MAX;
                #pragma unroll
                for (int nt = 0; nt < 8; nt++)
                    mx = fmaxf(mx, fmaxf(S[mt][nt][u*2], S[mt][nt][u*2+1]));
                mx = fmaxf(mx, __shfl_xor_sync(0xffffffffu, mx, 1));
                mx = fmaxf(mx, __shfl_xor_sync(0xffffffffu, mx, 2));
                float mn   = fmaxf(mrow[mt][u], mx);
                float corr = __expf(mrow[mt][u] - mn);
                mrow[mt][u] = mn;
                lrow[mt][u] *= corr;
                #pragma unroll
                for (int ntd = 0; ntd < 4; ntd++) {
                    Of[mt][ntd][u*2]   *= corr;
                    Of[mt][ntd][u*2+1] *= corr;
                }
                float ps = 0.f;
                #pragma unroll
                for (int nt = 0; nt < 8; nt++) {
                    float p0 = __expf(S[mt][nt][u*2]   - mn);
                    float p1 = __expf(S[mt][nt][u*2+1] - mn);
                    S[mt][nt][u*2]   = p0;
                    S[mt][nt][u*2+1] = p1;
                    ps += p0 + p1;
                }
                ps += __shfl_xor_sync(0xffffffffu, ps, 1);
                ps += __shfl_xor_sync(0xffffffffu, ps, 2);
                lrow[mt][u] += ps;
            }
        // ---- O += P V ----
        #pragma unroll
        for (int kstep = 0; kstep < 8; kstep++) {
            uint32_t bv0[4], bv1[4];
            #pragma unroll
            for (int ntd = 0; ntd < 4; ntd++) {
                bv0[ntd] = f2tf(Vs[(kc + kstep*8 + t    )*VS_STR + ntd*8 + g]);
                bv1[ntd] = f2tf(Vs[(kc + kstep*8 + t + 4)*VS_STR + ntd*8 + g]);
            }
            int base = lane & ~3;
            #pragma unroll
            for (int mt = 0; mt < 2; mt++) {
                // remap D-frag (P) -> A-frag via shfl butterfly
                float d0 = S[mt][kstep][0], d1 = S[mt][kstep][1];
                float d2 = S[mt][kstep][2], d3 = S[mt][kstep][3];
                float s00 = __shfl_sync(0xffffffffu, d0, base | (t >> 1));
                float s01 = __shfl_sync(0xffffffffu, d1, base | (t >> 1));
                float s02 = __shfl_sync(0xffffffffu, d0, base | ((t >> 1) + 2));
                float s03 = __shfl_sync(0xffffffffu, d1, base | ((t >> 1) + 2));
                float s10 = __shfl_sync(0xffffffffu, d2, base | (t >> 1));
                float s11 = __shfl_sync(0xffffffffu, d3, base | (t >> 1));
                float s12 = __shfl_sync(0xffffffffu, d2, base | ((t >> 1) + 2));
                float s13 = __shfl_sync(0xffffffffu, d3, base | ((t >> 1) + 2));
                uint32_t ap[4];
                ap[0] = f2tf((t & 1) ? s01 : s00);
                ap[1] = f2tf((t & 1) ? s11 : s10);
                ap[2] = f2tf((t & 1) ? s03 : s02);
                ap[3] = f2tf((t & 1) ? s13 : s12);
                #pragma unroll
                for (int ntd = 0; ntd < 4; ntd++)
                    mma_tf32(Of[mt][ntd], ap, bv0[ntd], bv1[ntd]);
            }
        }
    }

    // ---- epilogue: normalize and store ----
    float* obase = g_o + (size_t)(I*NN)*HD + h*DD;
    #pragma unroll
    for (int mt = 0; mt < 2; mt++) {
        float inv0 = 1.0f / lrow[mt][0];
        float inv1 = 1.0f / lrow[mt][1];
        int row0 = q0 + mt*16 + g;
        int row1 = row0 + 8;
        #pragma unroll
        for (int ntd = 0; ntd < 4; ntd++) {
            int col = ntd*8 + t*2;
            float2 w0 = make_float2(Of[mt][ntd][0]*inv0, Of[mt][ntd][1]*inv0);
            float2 w1 = make_float2(Of[mt][ntd][2]*inv1, Of[mt][ntd][3]*inv1);
            *(float2*)&obase[row0*HD + col] = w0;
            *(float2*)&obase[row1*HD + col] = w1;
        }
    }
}

// ---------------------------------------------------------------
// Kernel 5: gated output projection, 128x128 tile, 8x8 micro-tile
// ---------------------------------------------------------------
__global__ __launch_bounds__(256, 2)
void gemm_out(const float* __restrict__ bg, const float* __restrict__ bo,
              float* __restrict__ out)
{
    int m0 = blockIdx.x * 128;

    __shared__ float As[16][128];
    __shared__ float Bs[16][128];

    int tid = threadIdx.x;
    int tm = tid >> 4;
    int tn = tid & 15;

    float acc[8][8] = {};

    for (int k0 = 0; k0 < HD; k0 += 16) {
        #pragma unroll
        for (int i = 0; i < 2; i++) {
            int f = tid*2 + i;
            int r  = f >> 2;
            int kq = (f & 3) * 4;
            int row = m0 + r;
            float4 o4  = *(const float4*)&g_o[row*HD + k0 + kq];
            float4 g4  = *(const float4*)&g_g[row*HD + k0 + kq];
            float4 bg4 = *(const float4*)&bg[k0 + kq];
            As[kq+0][r] = o4.x / (1.0f + __expf(-(g4.x + bg4.x)));
            As[kq+1][r] = o4.y / (1.0f + __expf(-(g4.y + bg4.y)));
            As[kq+2][r] = o4.z / (1.0f + __expf(-(g4.z + bg4.z)));
            As[kq+3][r] = o4.w / (1.0f + __expf(-(g4.w + bg4.w)));
            int kr = f >> 5;
            int nq = (f & 31) * 4;
            *(float4*)&Bs[kr][nq] = *(const float4*)&g_woT[(k0 + kr)*HD + nq];
        }
        __syncthreads();
        #pragma unroll
        for (int kk = 0; kk < 16; kk++) {
            float a[8], b[8];
            *(float4*)&a[0] = *(const float4*)&As[kk][tm*8];
            *(float4*)&a[4] = *(const float4*)&As[kk][tm*8+4];
            *(float4*)&b[0] = *(const float4*)&Bs[kk][tn*8];
            *(float4*)&b[4] = *(const float4*)&Bs[kk][tn*8+4];
            #pragma unroll
            for (int i = 0; i < 8; i++)
                #pragma unroll
                for (int jx = 0; jx < 8; jx++)
                    acc[i][jx] += a[i] * b[jx];
        }
        __syncthreads();
    }

    #pragma unroll
    for (int i = 0; i < 8; i++) {
        int m  = m0 + tm*8 + i;
        int i1 = m >> 8, i2 = m & 255;
        int orow = i2*NN + i1;          // final swapaxes
        #pragma unroll
        for (int jq = 0; jq < 2; jq++) {
            float4 bo4 = *(const float4*)&bo[tn*8 + jq*4];
            float4 r4 = make_float4(acc[i][jq*4+0] + bo4.x, acc[i][jq*4+1] + bo4.y,
                                    acc[i][jq*4+2] + bo4.z, acc[i][jq*4+3] + bo4.w);
            *(float4*)&out[orow*CC + tn*8 + jq*4] = r4;
        }
    }
}

// ---------------------------------------------------------------
extern "C" void kernel_launch(void* const* d_in, const int* in_sizes, int n_in,
                              void* d_out, int out_size)
{
    const float* x      = (const float*)d_in[0];
    const float* mask   = (const float*)d_in[1];
    const float* ln_w   = (const float*)d_in[2];
    const float* ln_b   = (const float*)d_in[3];
    const float* w_bias = (const float*)d_in[4];
    const float* wq     = (const float*)d_in[5];
    const float* wk     = (const float*)d_in[6];
    const float* wv     = (const float*)d_in[7];
    const float* wg     = (const float*)d_in[8];
    const float* bg     = (const float*)d_in[9];
    const float* wo     = (const float*)d_in[10];
    const float* bo     = (const float*)d_in[11];
    float* out = (float*)d_out;

    static bool attr_set = false;
    if (!attr_set) {
        cudaFuncSetAttribute(attn_mma, cudaFuncAttributeMaxDynamicSharedMemorySize,
                             ATTN_SMEM);
        attr_set = true;
    }

    ln_kernel<<<MM, 128>>>(x, ln_w, ln_b, w_bias);
    gemm_proj<<<dim3(MM/128, 1, 4), 256>>>(wq, wk, wv, wg);
    transpose_wo<<<64, 256>>>(wo);
    attn_mma<<<dim3(NN, HH), 256, ATTN_SMEM>>>(mask);
    gemm_out<<<dim3(MM/128, 1), 256>>>(bg, bo, out);
}

// round 6
// speedup vs baseline: 2.4993x; 1.5861x over previous
#include <cuda_runtime.h>
#include <math.h>
#include <float.h>
#include <stdint.h>

#define NN 256
#define CC 128
#define HH 4
#define DD 32
#define MM (NN*NN)     // 65536
#define HD (HH*DD)     // 128
#define INF_ 1e9f
#define LN_EPS 1e-5f

// ---- scratch (no allocation allowed) ----
__device__ float g_xn[MM*CC];       // tf32-rounded
__device__ float g_q [MM*HD];       // tf32-rounded, scale applied
__device__ float g_k [MM*HD];       // tf32-rounded
__device__ float g_v [MM*HD];       // tf32-rounded
__device__ float g_g [MM*HD];       // tf32-rounded (gate pre-sigmoid input)
__device__ float g_o [MM*HD];       // fp32
__device__ float g_tbt[HH*NN*NN];   // [h][k][j], fp32
__device__ float g_woT[CC*HD];      // [k][n] = wo[n][k]

// ---------------------------------------------------------------
// tf32 helpers
// ---------------------------------------------------------------
__device__ __forceinline__ uint32_t f2tf(float x) {
    uint32_t r;
    asm("cvt.rna.tf32.f32 %0, %1;" : "=r"(r) : "f"(x));
    return r;
}
__device__ __forceinline__ float f2tf_f(float x) {
    return __uint_as_float(f2tf(x));
}

__device__ __forceinline__ void mma_tf32(float c[4], const uint32_t a[4],
                                         uint32_t b0, uint32_t b1) {
    asm volatile(
        "mma.sync.aligned.m16n8k8.row.col.f32.tf32.tf32.f32 "
        "{%0,%1,%2,%3}, {%4,%5,%6,%7}, {%8,%9}, {%0,%1,%2,%3};\n"
        : "+f"(c[0]), "+f"(c[1]), "+f"(c[2]), "+f"(c[3])
        : "r"(a[0]), "r"(a[1]), "r"(a[2]), "r"(a[3]), "r"(b0), "r"(b1));
}

// ---------------------------------------------------------------
// Kernel 1: LayerNorm (warp per row) + triangle-bias dots
// ---------------------------------------------------------------
__global__ __launch_bounds__(256)
void ln_kernel(const float* __restrict__ x,
               const float* __restrict__ ln_w,
               const float* __restrict__ ln_b,
               const float* __restrict__ w_bias)
{
    int warp = threadIdx.x >> 5, lane = threadIdx.x & 31;
    int m  = blockIdx.x * 8 + warp;
    int i1 = m >> 8;
    int i2 = m & 255;

    float4 v4 = *(const float4*)&x[(i2*NN + i1)*CC + lane*4];

    float s = v4.x + v4.y + v4.z + v4.w;
    #pragma unroll
    for (int o = 16; o > 0; o >>= 1) s += __shfl_xor_sync(0xffffffffu, s, o);
    float mu = s * (1.0f / CC);

    float dx = v4.x - mu, dy = v4.y - mu, dz = v4.z - mu, dw = v4.w - mu;
    float s2 = dx*dx + dy*dy + dz*dz + dw*dw;
    #pragma unroll
    for (int o = 16; o > 0; o >>= 1) s2 += __shfl_xor_sync(0xffffffffu, s2, o);
    float rs = rsqrtf(s2 * (1.0f / CC) + LN_EPS);

    float4 w4 = *(const float4*)&ln_w[lane*4];
    float4 b4 = *(const float4*)&ln_b[lane*4];
    float xn0 = dx*rs*w4.x + b4.x;
    float xn1 = dy*rs*w4.y + b4.y;
    float xn2 = dz*rs*w4.z + b4.z;
    float xn3 = dw*rs*w4.w + b4.w;

    *(float4*)&g_xn[m*CC + lane*4] =
        make_float4(f2tf_f(xn0), f2tf_f(xn1), f2tf_f(xn2), f2tf_f(xn3));

    // triangle bias dots (full precision)
    float acc[4];
    #pragma unroll
    for (int h = 0; h < 4; h++) {
        float4 wb = *(const float4*)&w_bias[h*CC + lane*4];
        acc[h] = xn0*wb.x + xn1*wb.y + xn2*wb.z + xn3*wb.w;
    }
    #pragma unroll
    for (int o = 16; o > 0; o >>= 1) {
        #pragma unroll
        for (int h = 0; h < 4; h++)
            acc[h] += __shfl_xor_sync(0xffffffffu, acc[h], o);
    }
    if (lane < 4)   // lane h writes head h (values identical across lanes)
        g_tbt[(lane*NN + i2)*NN + i1] = acc[lane];
}

// ---------------------------------------------------------------
// Kernel 2: fused q/k/v/g projections, tf32 mma.
// grid (M/128, 4). Block tile 128(M)x128(N), K staged by 32, dbl-buffered.
// As[m][k] stride 36; Bs[k][n] stride 136 (both conflict-free).
// ---------------------------------------------------------------
#define AS_STR 36
#define BS_STR 136
#define AS_SZ (128*AS_STR)          // 4608 floats / stage
#define BS_SZ (32*BS_STR)           // 4352 floats / stage
#define PROJ_SMEM ((AS_SZ + BS_SZ)*2*4)

__global__ __launch_bounds__(256, 2)
void gemm_proj_tf32(const float* __restrict__ W0, const float* __restrict__ W1,
                    const float* __restrict__ W2, const float* __restrict__ W3)
{
    extern __shared__ float ps[];
    float* As = ps;                      // [2][128][36]
    float* Bs = ps + 2*AS_SZ;            // [2][32][136]

    const float* W;
    float* Out;
    float osc = 1.0f;
    switch (blockIdx.y) {
        case 0: W = W0; Out = g_q; osc = 0.17677669529663689f; break;
        case 1: W = W1; Out = g_k; break;
        case 2: W = W2; Out = g_v; break;
        default: W = W3; Out = g_g; break;
    }
    int m0 = blockIdx.x * 128;

    int tid = threadIdx.x;
    int warp = tid >> 5, lane = tid & 31;
    int g = lane >> 2, t = lane & 3;
    int wm = warp >> 2, wn = warp & 3;   // warp tile 64x32
    int mbase = wm*64, nbase = wn*32;

    float acc[4][4][4] = {};

    // stage loader
    auto load_stage = [&](int buf, int k0) {
        float* A = As + buf*AS_SZ;
        float* B = Bs + buf*BS_SZ;
        #pragma unroll
        for (int i = 0; i < 4; i++) {
            int f = tid + 256*i;           // 0..1023
            int mm = f >> 3;               // 0..127
            int kq = (f & 7) * 4;
            float4 a = *(const float4*)&g_xn[(m0 + mm)*CC + k0 + kq];
            *(float4*)&A[mm*AS_STR + kq] = a;   // already tf32-rounded
            int kk = f >> 5;               // 0..31
            int nq = (f & 31) * 4;
            float4 b = *(const float4*)&W[(k0 + kk)*HD + nq];
            b.x = f2tf_f(b.x); b.y = f2tf_f(b.y);
            b.z = f2tf_f(b.z); b.w = f2tf_f(b.w);
            *(float4*)&B[kk*BS_STR + nq] = b;
        }
    };

    load_stage(0, 0);
    __syncthreads();

    for (int st = 0; st < 4; st++) {
        if (st < 3) load_stage((st + 1) & 1, (st + 1) * 32);
        float* A = As + (st & 1)*AS_SZ;
        float* B = Bs + (st & 1)*BS_SZ;
        #pragma unroll
        for (int ks = 0; ks < 4; ks++) {
            uint32_t af[4][4];
            #pragma unroll
            for (int mt = 0; mt < 4; mt++) {
                int r0 = mbase + mt*16 + g;
                af[mt][0] = __float_as_uint(A[ r0     *AS_STR + ks*8 + t    ]);
                af[mt][1] = __float_as_uint(A[(r0 + 8)*AS_STR + ks*8 + t    ]);
                af[mt][2] = __float_as_uint(A[ r0     *AS_STR + ks*8 + t + 4]);
                af[mt][3] = __float_as_uint(A[(r0 + 8)*AS_STR + ks*8 + t + 4]);
            }
            uint32_t bf0[4], bf1[4];
            #pragma unroll
            for (int nt = 0; nt < 4; nt++) {
                int nc = nbase + nt*8 + g;
                bf0[nt] = __float_as_uint(B[(ks*8 + t    )*BS_STR + nc]);
                bf1[nt] = __float_as_uint(B[(ks*8 + t + 4)*BS_STR + nc]);
            }
            #pragma unroll
            for (int mt = 0; mt < 4; mt++)
                #pragma unroll
                for (int nt = 0; nt < 4; nt++)
                    mma_tf32(acc[mt][nt], af[mt], bf0[nt], bf1[nt]);
        }
        __syncthreads();
    }

    // epilogue: scale, round to tf32, store
    #pragma unroll
    for (int mt = 0; mt < 4; mt++) {
        int row0 = m0 + mbase + mt*16 + g;
        int row1 = row0 + 8;
        #pragma unroll
        for (int nt = 0; nt < 4; nt++) {
            int col = nbase + nt*8 + 2*t;
            float2 w0 = make_float2(f2tf_f(acc[mt][nt][0]*osc), f2tf_f(acc[mt][nt][1]*osc));
            float2 w1 = make_float2(f2tf_f(acc[mt][nt][2]*osc), f2tf_f(acc[mt][nt][3]*osc));
            *(float2*)&Out[row0*HD + col] = w0;
            *(float2*)&Out[row1*HD + col] = w1;
        }
    }
}

// ---------------------------------------------------------------
// Kernel 3: wo transpose
// ---------------------------------------------------------------
__global__ void transpose_wo(const float* __restrict__ wo)
{
    int idx = blockIdx.x * 256 + threadIdx.x;
    int n = idx >> 7, k = idx & 127;
    g_woT[k*HD + n] = wo[n*HD + k];
}

// ---------------------------------------------------------------
// Kernel 4: tf32 mma flash attention (q/k/v pre-rounded -> no cvt)
// ---------------------------------------------------------------
#define KS_STR 36
#define VS_STR 40
#define ATTN_SMEM ((NN*KS_STR + NN*VS_STR + NN) * 4)

__global__ __launch_bounds__(256, 1)
void attn_mma(const float* __restrict__ mask)
{
    extern __shared__ float sm[];
    float* Ks = sm;                         // [256][36]
    float* Vs = sm + NN*KS_STR;             // [256][40]
    float* mb = sm + NN*KS_STR + NN*VS_STR; // [256]

    int I = blockIdx.x, h = blockIdx.y;
    int tid  = threadIdx.x;
    int warp = tid >> 5, lane = tid & 31;
    int g = lane >> 2, t = lane & 3;

    const float* kbase = g_k + (size_t)(I*NN)*HD + h*DD;
    const float* vbase = g_v + (size_t)(I*NN)*HD + h*DD;
    #pragma unroll
    for (int p = 0; p < 8; p++) {
        int slot = p*256 + tid;
        int key = slot >> 3;
        int d4  = (slot & 7) * 4;
        *(float4*)&Ks[key*KS_STR + d4] = *(const float4*)&kbase[key*HD + d4];
        *(float4*)&Vs[key*VS_STR + d4] = *(const float4*)&vbase[key*HD + d4];
    }
    mb[tid] = INF_ * (mask[tid*NN + I] - 1.0f);

    int q0 = warp * 32;
    const float* qbase = g_q + (size_t)(I*NN)*HD + h*DD;
    uint32_t aq[2][4][4];
    #pragma unroll
    for (int mt = 0; mt < 2; mt++)
        #pragma unroll
        for (int ks = 0; ks < 4; ks++)
            #pragma unroll
            for (int r = 0; r < 4; r++) {
                int row = q0 + mt*16 + (r & 1)*8 + g;
                int col = ks*8 + t + (r >> 1)*4;
                aq[mt][ks][r] = __float_as_uint(qbase[row*HD + col]);
            }

    float Of[2][4][4] = {};
    float mrow[2][2] = {{-FLT_MAX, -FLT_MAX}, {-FLT_MAX, -FLT_MAX}};
    float lrow[2][2] = {{0.f, 0.f}, {0.f, 0.f}};

    const float* tbp = g_tbt + h*NN*NN;

    __syncthreads();

    for (int kc = 0; kc < NN; kc += 64) {
        float S[2][8][4] = {};
        #pragma unroll
        for (int nt = 0; nt < 8; nt++) {
            int n0 = kc + nt*8;
            #pragma unroll
            for (int ks = 0; ks < 4; ks++) {
                uint32_t b0 = __float_as_uint(Ks[(n0 + g)*KS_STR + ks*8 + t]);
                uint32_t b1 = __float_as_uint(Ks[(n0 + g)*KS_STR + ks*8 + t + 4]);
                mma_tf32(S[0][nt], aq[0][ks], b0, b1);
                mma_tf32(S[1][nt], aq[1][ks], b0, b1);
            }
        }
        #pragma unroll
        for (int mt = 0; mt < 2; mt++)
            #pragma unroll
            for (int nt = 0; nt < 8; nt++)
                #pragma unroll
                for (int r = 0; r < 4; r++) {
                    int k   = kc + nt*8 + t*2 + (r & 1);
                    int row = q0 + mt*16 + (r >> 1)*8 + g;
                    S[mt][nt][r] += mb[k] + tbp[k*NN + row];
                }
        #pragma unroll
        for (int mt = 0; mt < 2; mt++)
            #pragma unroll
            for (int u = 0; u < 2; u++) {
                float mx = -FLT_MAX;
                #pragma unroll
                for (int nt = 0; nt < 8; nt++)
                    mx = fmaxf(mx, fmaxf(S[mt][nt][u*2], S[mt][nt][u*2+1]));
                mx = fmaxf(mx, __shfl_xor_sync(0xffffffffu, mx, 1));
                mx = fmaxf(mx, __shfl_xor_sync(0xffffffffu, mx, 2));
                float mn   = fmaxf(mrow[mt][u], mx);
                float corr = __expf(mrow[mt][u] - mn);
                mrow[mt][u] = mn;
                lrow[mt][u] *= corr;
                #pragma unroll
                for (int ntd = 0; ntd < 4; ntd++) {
                    Of[mt][ntd][u*2]   *= corr;
                    Of[mt][ntd][u*2+1] *= corr;
                }
                float ps = 0.f;
                #pragma unroll
                for (int nt = 0; nt < 8; nt++) {
                    float p0 = __expf(S[mt][nt][u*2]   - mn);
                    float p1 = __expf(S[mt][nt][u*2+1] - mn);
                    S[mt][nt][u*2]   = p0;
                    S[mt][nt][u*2+1] = p1;
                    ps += p0 + p1;
                }
                ps += __shfl_xor_sync(0xffffffffu, ps, 1);
                ps += __shfl_xor_sync(0xffffffffu, ps, 2);
                lrow[mt][u] += ps;
            }
        #pragma unroll
        for (int kstep = 0; kstep < 8; kstep++) {
            uint32_t bv0[4], bv1[4];
            #pragma unroll
            for (int ntd = 0; ntd < 4; ntd++) {
                bv0[ntd] = __float_as_uint(Vs[(kc + kstep*8 + t    )*VS_STR + ntd*8 + g]);
                bv1[ntd] = __float_as_uint(Vs[(kc + kstep*8 + t + 4)*VS_STR + ntd*8 + g]);
            }
            int base = lane & ~3;
            #pragma unroll
            for (int mt = 0; mt < 2; mt++) {
                float d0 = S[mt][kstep][0], d1 = S[mt][kstep][1];
                float d2 = S[mt][kstep][2], d3 = S[mt][kstep][3];
                float s00 = __shfl_sync(0xffffffffu, d0, base | (t >> 1));
                float s01 = __shfl_sync(0xffffffffu, d1, base | (t >> 1));
                float s02 = __shfl_sync(0xffffffffu, d0, base | ((t >> 1) + 2));
                float s03 = __shfl_sync(0xffffffffu, d1, base | ((t >> 1) + 2));
                float s10 = __shfl_sync(0xffffffffu, d2, base | (t >> 1));
                float s11 = __shfl_sync(0xffffffffu, d3, base | (t >> 1));
                float s12 = __shfl_sync(0xffffffffu, d2, base | ((t >> 1) + 2));
                float s13 = __shfl_sync(0xffffffffu, d3, base | ((t >> 1) + 2));
                uint32_t ap[4];
                ap[0] = f2tf((t & 1) ? s01 : s00);
                ap[1] = f2tf((t & 1) ? s11 : s10);
                ap[2] = f2tf((t & 1) ? s03 : s02);
                ap[3] = f2tf((t & 1) ? s13 : s12);
                #pragma unroll
                for (int ntd = 0; ntd < 4; ntd++)
                    mma_tf32(Of[mt][ntd], ap, bv0[ntd], bv1[ntd]);
            }
        }
    }

    float* obase = g_o + (size_t)(I*NN)*HD + h*DD;
    #pragma unroll
    for (int mt = 0; mt < 2; mt++) {
        float inv0 = 1.0f / lrow[mt][0];
        float inv1 = 1.0f / lrow[mt][1];
        int row0 = q0 + mt*16 + g;
        int row1 = row0 + 8;
        #pragma unroll
        for (int ntd = 0; ntd < 4; ntd++) {
            int col = ntd*8 + t*2;
            float2 w0 = make_float2(Of[mt][ntd][0]*inv0, Of[mt][ntd][1]*inv0);
            float2 w1 = make_float2(Of[mt][ntd][2]*inv1, Of[mt][ntd][3]*inv1);
            *(float2*)&obase[row0*HD + col] = w0;
            *(float2*)&obase[row1*HD + col] = w1;
        }
    }
}

// ---------------------------------------------------------------
// Kernel 5: gated output projection (SIMT fp32, keeps error margin)
// ---------------------------------------------------------------
__global__ __launch_bounds__(256, 2)
void gemm_out(const float* __restrict__ bg, const float* __restrict__ bo,
              float* __restrict__ out)
{
    int m0 = blockIdx.x * 128;

    __shared__ float As[16][128];
    __shared__ float Bs[16][128];

    int tid = threadIdx.x;
    int tm = tid >> 4;
    int tn = tid & 15;

    float acc[8][8] = {};

    for (int k0 = 0; k0 < HD; k0 += 16) {
        #pragma unroll
        for (int i = 0; i < 2; i++) {
            int f = tid*2 + i;
            int r  = f >> 2;
            int kq = (f & 3) * 4;
            int row = m0 + r;
            float4 o4  = *(const float4*)&g_o[row*HD + k0 + kq];
            float4 g4  = *(const float4*)&g_g[row*HD + k0 + kq];
            float4 bg4 = *(const float4*)&bg[k0 + kq];
            As[kq+0][r] = o4.x / (1.0f + __expf(-(g4.x + bg4.x)));
            As[kq+1][r] = o4.y / (1.0f + __expf(-(g4.y + bg4.y)));
            As[kq+2][r] = o4.z / (1.0f + __expf(-(g4.z + bg4.z)));
            As[kq+3][r] = o4.w / (1.0f + __expf(-(g4.w + bg4.w)));
            int kr = f >> 5;
            int nq = (f & 31) * 4;
            *(float4*)&Bs[kr][nq] = *(const float4*)&g_woT[(k0 + kr)*HD + nq];
        }
        __syncthreads();
        #pragma unroll
        for (int kk = 0; kk < 16; kk++) {
            float a[8], b[8];
            *(float4*)&a[0] = *(const float4*)&As[kk][tm*8];
            *(float4*)&a[4] = *(const float4*)&As[kk][tm*8+4];
            *(float4*)&b[0] = *(const float4*)&Bs[kk][tn*8];
            *(float4*)&b[4] = *(const float4*)&Bs[kk][tn*8+4];
            #pragma unroll
            for (int i = 0; i < 8; i++)
                #pragma unroll
                for (int jx = 0; jx < 8; jx++)
                    acc[i][jx] += a[i] * b[jx];
        }
        __syncthreads();
    }

    #pragma unroll
    for (int i = 0; i < 8; i++) {
        int m  = m0 + tm*8 + i;
        int i1 = m >> 8, i2 = m & 255;
        int orow = i2*NN + i1;          // final swapaxes
        #pragma unroll
        for (int jq = 0; jq < 2; jq++) {
            float4 bo4 = *(const float4*)&bo[tn*8 + jq*4];
            float4 r4 = make_float4(acc[i][jq*4+0] + bo4.x, acc[i][jq*4+1] + bo4.y,
                                    acc[i][jq*4+2] + bo4.z, acc[i][jq*4+3] + bo4.w);
            *(float4*)&out[orow*CC + tn*8 + jq*4] = r4;
        }
    }
}

// ---------------------------------------------------------------
extern "C" void kernel_launch(void* const* d_in, const int* in_sizes, int n_in,
                              void* d_out, int out_size)
{
    const float* x      = (const float*)d_in[0];
    const float* mask   = (const float*)d_in[1];
    const float* ln_w   = (const float*)d_in[2];
    const float* ln_b   = (const float*)d_in[3];
    const float* w_bias = (const float*)d_in[4];
    const float* wq     = (const float*)d_in[5];
    const float* wk     = (const float*)d_in[6];
    const float* wv     = (const float*)d_in[7];
    const float* wg     = (const float*)d_in[8];
    const float* bg     = (const float*)d_in[9];
    const float* wo     = (const float*)d_in[10];
    const float* bo     = (const float*)d_in[11];
    float* out = (float*)d_out;

    static bool attr_set = false;
    if (!attr_set) {
        cudaFuncSetAttribute(attn_mma, cudaFuncAttributeMaxDynamicSharedMemorySize,
                             ATTN_SMEM);
        cudaFuncSetAttribute(gemm_proj_tf32, cudaFuncAttributeMaxDynamicSharedMemorySize,
                             PROJ_SMEM);
        attr_set = true;
    }

    ln_kernel<<<MM/8, 256>>>(x, ln_w, ln_b, w_bias);
    gemm_proj_tf32<<<dim3(MM/128, 4), 256, PROJ_SMEM>>>(wq, wk, wv, wg);
    transpose_wo<<<64, 256>>>(wo);
    attn_mma<<<dim3(NN, HH), 256, ATTN_SMEM>>>(mask);
    gemm_out<<<dim3(MM/128, 1), 256>>>(bg, bo, out);
}

// round 7
// speedup vs baseline: 2.7676x; 1.1073x over previous
#include <cuda_runtime.h>
#include <math.h>
#include <float.h>
#include <stdint.h>

#define NN 256
#define CC 128
#define HH 4
#define DD 32
#define MM (NN*NN)     // 65536
#define HD (HH*DD)     // 128
#define INF_ 1e9f
#define LN_EPS 1e-5f

// ---- scratch (no allocation allowed) ----
__device__ float g_xn[MM*CC];       // tf32-rounded
__device__ float g_q [MM*HD];       // tf32-rounded, scale applied
__device__ float g_k [MM*HD];       // tf32-rounded
__device__ float g_v [MM*HD];       // tf32-rounded
__device__ float g_g [MM*HD];       // gate pre-sigmoid input
__device__ float g_o [MM*HD];       // fp32
__device__ float g_tbt[HH*NN*NN];   // [h][j][k], fp32
__device__ float g_woT[CC*HD];      // [k][n] = wo[n][k]

// ---------------------------------------------------------------
// tf32 helpers
// ---------------------------------------------------------------
__device__ __forceinline__ uint32_t f2tf(float x) {
    uint32_t r;
    asm("cvt.rna.tf32.f32 %0, %1;" : "=r"(r) : "f"(x));
    return r;
}
__device__ __forceinline__ float f2tf_f(float x) {
    return __uint_as_float(f2tf(x));
}

__device__ __forceinline__ void mma_tf32(float c[4], const uint32_t a[4],
                                         uint32_t b0, uint32_t b1) {
    asm volatile(
        "mma.sync.aligned.m16n8k8.row.col.f32.tf32.tf32.f32 "
        "{%0,%1,%2,%3}, {%4,%5,%6,%7}, {%8,%9}, {%0,%1,%2,%3};\n"
        : "+f"(c[0]), "+f"(c[1]), "+f"(c[2]), "+f"(c[3])
        : "r"(a[0]), "r"(a[1]), "r"(a[2]), "r"(a[3]), "r"(b0), "r"(b1));
}

// ---------------------------------------------------------------
// Kernel 1: LayerNorm (warp per row) + triangle-bias dots
// ---------------------------------------------------------------
__global__ __launch_bounds__(256)
void ln_kernel(const float* __restrict__ x,
               const float* __restrict__ ln_w,
               const float* __restrict__ ln_b,
               const float* __restrict__ w_bias)
{
    int warp = threadIdx.x >> 5, lane = threadIdx.x & 31;
    int m  = blockIdx.x * 8 + warp;
    int i1 = m >> 8;
    int i2 = m & 255;

    float4 v4 = *(const float4*)&x[(i2*NN + i1)*CC + lane*4];

    float s = v4.x + v4.y + v4.z + v4.w;
    #pragma unroll
    for (int o = 16; o > 0; o >>= 1) s += __shfl_xor_sync(0xffffffffu, s, o);
    float mu = s * (1.0f / CC);

    float dx = v4.x - mu, dy = v4.y - mu, dz = v4.z - mu, dw = v4.w - mu;
    float s2 = dx*dx + dy*dy + dz*dz + dw*dw;
    #pragma unroll
    for (int o = 16; o > 0; o >>= 1) s2 += __shfl_xor_sync(0xffffffffu, s2, o);
    float rs = rsqrtf(s2 * (1.0f / CC) + LN_EPS);

    float4 w4 = *(const float4*)&ln_w[lane*4];
    float4 b4 = *(const float4*)&ln_b[lane*4];
    float xn0 = dx*rs*w4.x + b4.x;
    float xn1 = dy*rs*w4.y + b4.y;
    float xn2 = dz*rs*w4.z + b4.z;
    float xn3 = dw*rs*w4.w + b4.w;

    *(float4*)&g_xn[m*CC + lane*4] =
        make_float4(f2tf_f(xn0), f2tf_f(xn1), f2tf_f(xn2), f2tf_f(xn3));

    // triangle bias dots (full precision); layout [h][j=i1][k=i2]
    float acc[4];
    #pragma unroll
    for (int h = 0; h < 4; h++) {
        float4 wb = *(const float4*)&w_bias[h*CC + lane*4];
        acc[h] = xn0*wb.x + xn1*wb.y + xn2*wb.z + xn3*wb.w;
    }
    #pragma unroll
    for (int o = 16; o > 0; o >>= 1) {
        #pragma unroll
        for (int h = 0; h < 4; h++)
            acc[h] += __shfl_xor_sync(0xffffffffu, acc[h], o);
    }
    if (lane < 4)
        g_tbt[(lane*NN + i1)*NN + i2] = acc[lane];
}

// ---------------------------------------------------------------
// Kernel 2: fused q/k/v/g projections, tf32 mma.
// ---------------------------------------------------------------
#define AS_STR 36
#define BS_STR 136
#define AS_SZ (128*AS_STR)
#define BS_SZ (32*BS_STR)
#define PROJ_SMEM ((AS_SZ + BS_SZ)*2*4)

__global__ __launch_bounds__(256, 2)
void gemm_proj_tf32(const float* __restrict__ W0, const float* __restrict__ W1,
                    const float* __restrict__ W2, const float* __restrict__ W3)
{
    extern __shared__ float ps[];
    float* As = ps;
    float* Bs = ps + 2*AS_SZ;

    const float* W;
    float* Out;
    float osc = 1.0f;
    switch (blockIdx.y) {
        case 0: W = W0; Out = g_q; osc = 0.17677669529663689f; break;
        case 1: W = W1; Out = g_k; break;
        case 2: W = W2; Out = g_v; break;
        default: W = W3; Out = g_g; break;
    }
    int m0 = blockIdx.x * 128;

    int tid = threadIdx.x;
    int warp = tid >> 5, lane = tid & 31;
    int g = lane >> 2, t = lane & 3;
    int wm = warp >> 2, wn = warp & 3;
    int mbase = wm*64, nbase = wn*32;

    float acc[4][4][4] = {};

    auto load_stage = [&](int buf, int k0) {
        float* A = As + buf*AS_SZ;
        float* B = Bs + buf*BS_SZ;
        #pragma unroll
        for (int i = 0; i < 4; i++) {
            int f = tid + 256*i;
            int mm = f >> 3;
            int kq = (f & 7) * 4;
            float4 a = *(const float4*)&g_xn[(m0 + mm)*CC + k0 + kq];
            *(float4*)&A[mm*AS_STR + kq] = a;
            int kk = f >> 5;
            int nq = (f & 31) * 4;
            float4 b = *(const float4*)&W[(k0 + kk)*HD + nq];
            b.x = f2tf_f(b.x); b.y = f2tf_f(b.y);
            b.z = f2tf_f(b.z); b.w = f2tf_f(b.w);
            *(float4*)&B[kk*BS_STR + nq] = b;
        }
    };

    load_stage(0, 0);
    __syncthreads();

    for (int st = 0; st < 4; st++) {
        if (st < 3) load_stage((st + 1) & 1, (st + 1) * 32);
        float* A = As + (st & 1)*AS_SZ;
        float* B = Bs + (st & 1)*BS_SZ;
        #pragma unroll
        for (int ks = 0; ks < 4; ks++) {
            uint32_t af[4][4];
            #pragma unroll
            for (int mt = 0; mt < 4; mt++) {
                int r0 = mbase + mt*16 + g;
                af[mt][0] = __float_as_uint(A[ r0     *AS_STR + ks*8 + t    ]);
                af[mt][1] = __float_as_uint(A[(r0 + 8)*AS_STR + ks*8 + t    ]);
                af[mt][2] = __float_as_uint(A[ r0     *AS_STR + ks*8 + t + 4]);
                af[mt][3] = __float_as_uint(A[(r0 + 8)*AS_STR + ks*8 + t + 4]);
            }
            uint32_t bf0[4], bf1[4];
            #pragma unroll
            for (int nt = 0; nt < 4; nt++) {
                int nc = nbase + nt*8 + g;
                bf0[nt] = __float_as_uint(B[(ks*8 + t    )*BS_STR + nc]);
                bf1[nt] = __float_as_uint(B[(ks*8 + t + 4)*BS_STR + nc]);
            }
            #pragma unroll
            for (int mt = 0; mt < 4; mt++)
                #pragma unroll
                for (int nt = 0; nt < 4; nt++)
                    mma_tf32(acc[mt][nt], af[mt], bf0[nt], bf1[nt]);
        }
        __syncthreads();
    }

    #pragma unroll
    for (int mt = 0; mt < 4; mt++) {
        int row0 = m0 + mbase + mt*16 + g;
        int row1 = row0 + 8;
        #pragma unroll
        for (int nt = 0; nt < 4; nt++) {
            int col = nbase + nt*8 + 2*t;
            float2 w0 = make_float2(f2tf_f(acc[mt][nt][0]*osc), f2tf_f(acc[mt][nt][1]*osc));
            float2 w1 = make_float2(f2tf_f(acc[mt][nt][2]*osc), f2tf_f(acc[mt][nt][3]*osc));
            *(float2*)&Out[row0*HD + col] = w0;
            *(float2*)&Out[row1*HD + col] = w1;
        }
    }
}

// ---------------------------------------------------------------
// Kernel 3: wo transpose (tf32-round for mma consumer)
// ---------------------------------------------------------------
__global__ void transpose_wo(const float* __restrict__ wo)
{
    int idx = blockIdx.x * 256 + threadIdx.x;
    int n = idx >> 7, k = idx & 127;
    g_woT[k*HD + n] = f2tf_f(wo[n*HD + k]);
}

// ---------------------------------------------------------------
// Kernel 4: tf32 mma flash attention. 512 threads, 16 warps,
// each warp owns 16 query rows -> ~128 regs -> 16 warps/SM.
// ---------------------------------------------------------------
#define KS_STR 36
#define VS_STR 40
#define ATTN_SMEM ((NN*KS_STR + NN*VS_STR + NN) * 4)

__global__ __launch_bounds__(512, 1)
void attn_mma(const float* __restrict__ mask)
{
    extern __shared__ float sm[];
    float* Ks = sm;                         // [256][36]
    float* Vs = sm + NN*KS_STR;             // [256][40]
    float* mb = sm + NN*KS_STR + NN*VS_STR; // [256]

    int I = blockIdx.x, h = blockIdx.y;
    int tid  = threadIdx.x;
    int warp = tid >> 5, lane = tid & 31;
    int g = lane >> 2, t = lane & 3;

    const float* kbase = g_k + (size_t)(I*NN)*HD + h*DD;
    const float* vbase = g_v + (size_t)(I*NN)*HD + h*DD;
    #pragma unroll
    for (int p = 0; p < 4; p++) {
        int slot = p*512 + tid;             // 0..2047
        int key = slot >> 3;
        int d4  = (slot & 7) * 4;
        *(float4*)&Ks[key*KS_STR + d4] = *(const float4*)&kbase[key*HD + d4];
        *(float4*)&Vs[key*VS_STR + d4] = *(const float4*)&vbase[key*HD + d4];
    }
    if (tid < 256) mb[tid] = INF_ * (mask[tid*NN + I] - 1.0f);

    int q0 = warp * 16;
    const float* qbase = g_q + (size_t)(I*NN)*HD + h*DD;
    uint32_t aq[4][4];
    #pragma unroll
    for (int ks = 0; ks < 4; ks++)
        #pragma unroll
        for (int r = 0; r < 4; r++) {
            int row = q0 + (r & 1)*8 + g;
            int col = ks*8 + t + (r >> 1)*4;
            aq[ks][r] = __float_as_uint(qbase[row*HD + col]);
        }

    float Of[4][4] = {};
    float mrow[2] = {-FLT_MAX, -FLT_MAX};
    float lrow[2] = {0.f, 0.f};

    const float* tbp = g_tbt + h*NN*NN;     // [j][k]

    __syncthreads();

    for (int kc = 0; kc < NN; kc += 64) {
        // ---- S = Q K^T ----
        float S[8][4] = {};
        #pragma unroll
        for (int nt = 0; nt < 8; nt++) {
            int n0 = kc + nt*8;
            #pragma unroll
            for (int ks = 0; ks < 4; ks++) {
                uint32_t b0 = __float_as_uint(Ks[(n0 + g)*KS_STR + ks*8 + t]);
                uint32_t b1 = __float_as_uint(Ks[(n0 + g)*KS_STR + ks*8 + t + 4]);
                mma_tf32(S[nt], aq[ks], b0, b1);
            }
        }
        // ---- biases: coalesced float2 from [j][k] layout ----
        #pragma unroll
        for (int nt = 0; nt < 8; nt++) {
            int kcol = kc + nt*8 + t*2;
            float2 t0 = *(const float2*)&tbp[(q0 + g    )*NN + kcol];
            float2 t1 = *(const float2*)&tbp[(q0 + 8 + g)*NN + kcol];
            float m0v = mb[kcol], m1v = mb[kcol + 1];
            S[nt][0] += m0v + t0.x;  S[nt][1] += m1v + t0.y;
            S[nt][2] += m0v + t1.x;  S[nt][3] += m1v + t1.y;
        }
        // ---- online softmax per row-group u ----
        #pragma unroll
        for (int u = 0; u < 2; u++) {
            float mx = -FLT_MAX;
            #pragma unroll
            for (int nt = 0; nt < 8; nt++)
                mx = fmaxf(mx, fmaxf(S[nt][u*2], S[nt][u*2+1]));
            mx = fmaxf(mx, __shfl_xor_sync(0xffffffffu, mx, 1));
            mx = fmaxf(mx, __shfl_xor_sync(0xffffffffu, mx, 2));
            float mn   = fmaxf(mrow[u], mx);
            float corr = __expf(mrow[u] - mn);
            mrow[u] = mn;
            lrow[u] *= corr;
            #pragma unroll
            for (int ntd = 0; ntd < 4; ntd++) {
                Of[ntd][u*2]   *= corr;
                Of[ntd][u*2+1] *= corr;
            }
            float ps = 0.f;
            #pragma unroll
            for (int nt = 0; nt < 8; nt++) {
                float p0 = __expf(S[nt][u*2]   - mn);
                float p1 = __expf(S[nt][u*2+1] - mn);
                S[nt][u*2]   = p0;
                S[nt][u*2+1] = p1;
                ps += p0 + p1;
            }
            ps += __shfl_xor_sync(0xffffffffu, ps, 1);
            ps += __shfl_xor_sync(0xffffffffu, ps, 2);
            lrow[u] += ps;
        }
        // ---- O += P V ----
        #pragma unroll
        for (int kstep = 0; kstep < 8; kstep++) {
            uint32_t bv0[4], bv1[4];
            #pragma unroll
            for (int ntd = 0; ntd < 4; ntd++) {
                bv0[ntd] = __float_as_uint(Vs[(kc + kstep*8 + t    )*VS_STR + ntd*8 + g]);
                bv1[ntd] = __float_as_uint(Vs[(kc + kstep*8 + t + 4)*VS_STR + ntd*8 + g]);
            }
            int base = lane & ~3;
            float d0 = S[kstep][0], d1 = S[kstep][1];
            float d2 = S[kstep][2], d3 = S[kstep][3];
            float s00 = __shfl_sync(0xffffffffu, d0, base | (t >> 1));
            float s01 = __shfl_sync(0xffffffffu, d1, base | (t >> 1));
            float s02 = __shfl_sync(0xffffffffu, d0, base | ((t >> 1) + 2));
            float s03 = __shfl_sync(0xffffffffu, d1, base | ((t >> 1) + 2));
            float s10 = __shfl_sync(0xffffffffu, d2, base | (t >> 1));
            float s11 = __shfl_sync(0xffffffffu, d3, base | (t >> 1));
            float s12 = __shfl_sync(0xffffffffu, d2, base | ((t >> 1) + 2));
            float s13 = __shfl_sync(0xffffffffu, d3, base | ((t >> 1) + 2));
            uint32_t ap[4];
            ap[0] = f2tf((t & 1) ? s01 : s00);
            ap[1] = f2tf((t & 1) ? s11 : s10);
            ap[2] = f2tf((t & 1) ? s03 : s02);
            ap[3] = f2tf((t & 1) ? s13 : s12);
            #pragma unroll
            for (int ntd = 0; ntd < 4; ntd++)
                mma_tf32(Of[ntd], ap, bv0[ntd], bv1[ntd]);
        }
    }

    float* obase = g_o + (size_t)(I*NN)*HD + h*DD;
    float inv0 = 1.0f / lrow[0];
    float inv1 = 1.0f / lrow[1];
    int row0 = q0 + g;
    int row1 = row0 + 8;
    #pragma unroll
    for (int ntd = 0; ntd < 4; ntd++) {
        int col = ntd*8 + t*2;
        float2 w0 = make_float2(Of[ntd][0]*inv0, Of[ntd][1]*inv0);
        float2 w1 = make_float2(Of[ntd][2]*inv1, Of[ntd][3]*inv1);
        *(float2*)&obase[row0*HD + col] = w0;
        *(float2*)&obase[row1*HD + col] = w1;
    }
}

// ---------------------------------------------------------------
// Kernel 5: gated output projection, tf32 mma + scatter epilogue
// ---------------------------------------------------------------
__global__ __launch_bounds__(256, 2)
void gemm_out_tf32(const float* __restrict__ bg, const float* __restrict__ bo,
                   float* __restrict__ out)
{
    extern __shared__ float ps[];
    float* As = ps;
    float* Bs = ps + 2*AS_SZ;

    int m0 = blockIdx.x * 128;

    int tid = threadIdx.x;
    int warp = tid >> 5, lane = tid & 31;
    int g = lane >> 2, t = lane & 3;
    int wm = warp >> 2, wn = warp & 3;
    int mbase = wm*64, nbase = wn*32;

    float acc[4][4][4] = {};

    auto load_stage = [&](int buf, int k0) {
        float* A = As + buf*AS_SZ;
        float* B = Bs + buf*BS_SZ;
        #pragma unroll
        for (int i = 0; i < 4; i++) {
            int f = tid + 256*i;
            int mm = f >> 3;
            int kq = (f & 7) * 4;
            int row = m0 + mm;
            float4 o4  = *(const float4*)&g_o[row*HD + k0 + kq];
            float4 g4  = *(const float4*)&g_g[row*HD + k0 + kq];
            float4 bg4 = *(const float4*)&bg[k0 + kq];
            float4 a;
            a.x = f2tf_f(o4.x / (1.0f + __expf(-(g4.x + bg4.x))));
            a.y = f2tf_f(o4.y / (1.0f + __expf(-(g4.y + bg4.y))));
            a.z = f2tf_f(o4.z / (1.0f + __expf(-(g4.z + bg4.z))));
            a.w = f2tf_f(o4.w / (1.0f + __expf(-(g4.w + bg4.w))));
            *(float4*)&A[mm*AS_STR + kq] = a;
            int kk = f >> 5;
            int nq = (f & 31) * 4;
            *(float4*)&B[kk*BS_STR + nq] = *(const float4*)&g_woT[(k0 + kk)*HD + nq];
        }
    };

    load_stage(0, 0);
    __syncthreads();

    for (int st = 0; st < 4; st++) {
        if (st < 3) load_stage((st + 1) & 1, (st + 1) * 32);
        float* A = As + (st & 1)*AS_SZ;
        float* B = Bs + (st & 1)*BS_SZ;
        #pragma unroll
        for (int ks = 0; ks < 4; ks++) {
            uint32_t af[4][4];
            #pragma unroll
            for (int mt = 0; mt < 4; mt++) {
                int r0 = mbase + mt*16 + g;
                af[mt][0] = __float_as_uint(A[ r0     *AS_STR + ks*8 + t    ]);
                af[mt][1] = __float_as_uint(A[(r0 + 8)*AS_STR + ks*8 + t    ]);
                af[mt][2] = __float_as_uint(A[ r0     *AS_STR + ks*8 + t + 4]);
                af[mt][3] = __float_as_uint(A[(r0 + 8)*AS_STR + ks*8 + t + 4]);
            }
            uint32_t bf0[4], bf1[4];
            #pragma unroll
            for (int nt = 0; nt < 4; nt++) {
                int nc = nbase + nt*8 + g;
                bf0[nt] = __float_as_uint(B[(ks*8 + t    )*BS_STR + nc]);
                bf1[nt] = __float_as_uint(B[(ks*8 + t + 4)*BS_STR + nc]);
            }
            #pragma unroll
            for (int mt = 0; mt < 4; mt++)
                #pragma unroll
                for (int nt = 0; nt < 4; nt++)
                    mma_tf32(acc[mt][nt], af[mt], bf0[nt], bf1[nt]);
        }
        __syncthreads();
    }

    #pragma unroll
    for (int mt = 0; mt < 4; mt++) {
        int mr0 = m0 + mbase + mt*16 + g;
        int mr1 = mr0 + 8;
        int or0 = (mr0 & 255)*NN + (mr0 >> 8);   // swapaxes scatter
        int or1 = (mr1 & 255)*NN + (mr1 >> 8);
        #pragma unroll
        for (int nt = 0; nt < 4; nt++) {
            int col = nbase + nt*8 + 2*t;
            float2 b2 = *(const float2*)&bo[col];
            float2 w0 = make_float2(acc[mt][nt][0] + b2.x, acc[mt][nt][1] + b2.y);
            float2 w1 = make_float2(acc[mt][nt][2] + b2.x, acc[mt][nt][3] + b2.y);
            *(float2*)&out[or0*CC + col] = w0;
            *(float2*)&out[or1*CC + col] = w1;
        }
    }
}

// ---------------------------------------------------------------
extern "C" void kernel_launch(void* const* d_in, const int* in_sizes, int n_in,
                              void* d_out, int out_size)
{
    const float* x      = (const float*)d_in[0];
    const float* mask   = (const float*)d_in[1];
    const float* ln_w   = (const float*)d_in[2];
    const float* ln_b   = (const float*)d_in[3];
    const float* w_bias = (const float*)d_in[4];
    const float* wq     = (const float*)d_in[5];
    const float* wk     = (const float*)d_in[6];
    const float* wv     = (const float*)d_in[7];
    const float* wg     = (const float*)d_in[8];
    const float* bg     = (const float*)d_in[9];
    const float* wo     = (const float*)d_in[10];
    const float* bo     = (const float*)d_in[11];
    float* out = (float*)d_out;

    static bool attr_set = false;
    if (!attr_set) {
        cudaFuncSetAttribute(attn_mma, cudaFuncAttributeMaxDynamicSharedMemorySize,
                             ATTN_SMEM);
        cudaFuncSetAttribute(gemm_proj_tf32, cudaFuncAttributeMaxDynamicSharedMemorySize,
                             PROJ_SMEM);
        cudaFuncSetAttribute(gemm_out_tf32, cudaFuncAttributeMaxDynamicSharedMemorySize,
                             PROJ_SMEM);
        attr_set = true;
    }

    ln_kernel<<<MM/8, 256>>>(x, ln_w, ln_b, w_bias);
    gemm_proj_tf32<<<dim3(MM/128, 4), 256, PROJ_SMEM>>>(wq, wk, wv, wg);
    transpose_wo<<<64, 256>>>(wo);
    attn_mma<<<dim3(NN, HH), 512, ATTN_SMEM>>>(mask);
    gemm_out_tf32<<<dim3(MM/128, 1), 256, PROJ_SMEM>>>(bg, bo, out);
}